// round 13
// baseline (speedup 1.0000x reference)
#include <cuda_runtime.h>
#include <cuda_pipeline_primitives.h>

// Problem constants: S=128, D=512, H=8, W=64, NUM=16, SCALE=sqrt(8)
#define INV_SCALE 0.35355339059327373f
#define LOG2E     1.4426950408889634f

// Scratch (allocation-free rule: __device__ globals)
static __device__ float g_vp[128*512], g_qp[128*512], g_ap[128*512], g_kp[128*512];
static __device__ float g_vo[128*512], g_qo[128*512], g_ao[128*512], g_ko[128*512];
static __device__ float g_Rv[128*64],  g_Rq[128*64],  g_Ra[128*64];

// ---- packed f32x2 helpers (sm_103a: FFMA2 only reachable via PTX) ----------
__device__ __forceinline__ unsigned long long pk2(float x, float y) {
    unsigned long long r;
    asm("mov.b64 %0, {%1, %2};" : "=l"(r) : "f"(x), "f"(y));
    return r;
}
__device__ __forceinline__ void upk2(float& x, float& y, unsigned long long p) {
    asm("mov.b64 {%0, %1}, %2;" : "=f"(x), "=f"(y) : "l"(p));
}
__device__ __forceinline__ unsigned long long fma2(unsigned long long a,
                                                   unsigned long long b,
                                                   unsigned long long c) {
    unsigned long long d;
    asm("fma.rn.f32x2 %0, %1, %2, %3;" : "=l"(d) : "l"(a), "l"(b), "l"(c));
    return d;
}
__device__ __forceinline__ unsigned long long add2(unsigned long long a,
                                                   unsigned long long b) {
    unsigned long long d;
    asm("add.rn.f32x2 %0, %1, %2;" : "=l"(d) : "l"(a), "l"(b));
    return d;
}
__device__ __forceinline__ float ex2f(float x) {
    float r;
    asm("ex2.approx.f32 %0, %1;" : "=f"(r) : "f"(x));
    return r;
}

// ---- proj0 buffers (k-major, swizzled): As 32x32 (4096B) + Bs 64x32 (8192B)
#define PROJ0_BUF   12288
#define PROJ0_SMEM  (3*PROJ0_BUF)    // 36864 < 48KB static

// ---- fused-kernel proj buffers (R7/R9-proven layout, stride 33)
#define PROJ_BUF_BYTES 12928
#define FUSED_SMEM     (2*PROJ_BUF_BYTES)

// ---------------------------------------------------------------------------
// proj0: cp.async(16B) 3-stage pipelined GEMM.  C[32x64] = A[32x512]@W^T + b.
// R10-12 established the binder is LDGSTS store-side bank conflicts (4-way
// on every 4B copy).  Fix: k-major tiles (rows of 32 k-words = 128B) with a
// quad-XOR swizzle (quad ^= (row>>2)&7):
//   - fill: 3x cp.async.cg 16B per thread, conflict-free (one lane per
//     bank-quad per phase), gmem reads coalesced (16B contiguous in k)
//   - compute: k-quad micro-kernel; A LDS.128 = 2-addr broadcast (1 phase),
//     B LDS.128 = 16 distinct rows, 2-phase minimum via the tx-swizzle.
// 128 blocks x 256 threads (R10 grid).  2-way k-split (h = tid>>7: quads
// 4h..4h+3 of each chunk); halves merged via 8KB smem reduction.
// ---------------------------------------------------------------------------
__global__ __launch_bounds__(256) void proj0_kernel(
    const float* __restrict__ v, const float* __restrict__ q,
    const float* __restrict__ a, const float* __restrict__ k,
    const float* __restrict__ Wv, const float* __restrict__ Wq,
    const float* __restrict__ Wa, const float* __restrict__ Wk,
    const float* __restrict__ bv, const float* __restrict__ bq,
    const float* __restrict__ ba, const float* __restrict__ bk)
{
    __shared__ __align__(16) float sm[PROJ0_SMEM/4];
    const int p = blockIdx.z;
    const float* A    = (p==0)?v:(p==1)?q:(p==2)?a:k;
    const float* Wt   = (p==0)?Wv:(p==1)?Wq:(p==2)?Wa:Wk;
    const float* bias = (p==0)?bv:(p==1)?bq:(p==2)?ba:bk;
    float* C          = (p==0)?g_vp:(p==1)?g_qp:(p==2)?g_ap:g_kp;

    const int mbase = blockIdx.y * 32;
    const int nbase = blockIdx.x * 64;
    const int tid = threadIdx.x;
    const int tx = tid & 15;           // n-group (4 cols)
    const int my = (tid >> 4) & 7;     // m-group (4 rows)
    const int h  = tid >> 7;           // k-half: quads 4h..4h+3

    // ---- fill addressing (per-thread constants) ----
    // A unit: m = tid&31, qa = tid>>5 (0..7)
    const int fm = tid & 31, qa = tid >> 5;
    const float* srcA = A + (mbase + fm)*512 + 4*qa;
    const int dstA = fm*32 + 4*(qa ^ ((fm >> 2) & 7));
    // B units: n = tid&63, qb = tid>>6 (0..3) and qb+4
    const int fn = tid & 63, qb = tid >> 6;
    const float* srcB0 = Wt + (nbase + fn)*512 + 4*qb;
    const float* srcB1 = srcB0 + 16;
    const int swn = (fn >> 2) & 7;
    const int dstB0 = 1024 + fn*32 + 4*(qb ^ swn);
    const int dstB1 = 1024 + fn*32 + 4*((qb + 4) ^ swn);

    unsigned long long acc[4][2] = {{0,0},{0,0},{0,0},{0,0}};

    // pipelined fill helper (macro-ish lambda)
    auto issue = [&](int stage, int kofs) {
        float* buf = sm + stage*(PROJ0_BUF/4);
        __pipeline_memcpy_async(buf + dstA,  srcA  + kofs, 16);
        __pipeline_memcpy_async(buf + dstB0, srcB0 + kofs, 16);
        __pipeline_memcpy_async(buf + dstB1, srcB1 + kofs, 16);
    };

    issue(0, 0);  __pipeline_commit();
    issue(1, 32); __pipeline_commit();

    // compute addressing constants
    const int arow0 = (my*4)*32;           // A rows 4my..4my+3, stride 32
    const int aswz  = my & 7;              // (m>>2)&7 for m = 4my+f
    const int brow0 = 1024 + (tx*4)*32;    // B rows 4tx..4tx+3
    const int bswz  = tx & 7;              // (n>>2)&7 for n = 4tx+e

    #pragma unroll
    for (int kc = 0; kc < 16; kc++) {
        __pipeline_wait_prior(1);
        __syncthreads();
        const float* buf = sm + (kc % 3)*(PROJ0_BUF/4);
        #pragma unroll
        for (int jj = 0; jj < 4; jj++) {
            int j = h*4 + jj;
            float4 af[4], be[4];
            #pragma unroll
            for (int f = 0; f < 4; f++)
                af[f] = *(const float4*)(buf + arow0 + f*32 + 4*(j ^ aswz));
            #pragma unroll
            for (int e = 0; e < 4; e++)
                be[e] = *(const float4*)(buf + brow0 + e*32 + 4*(j ^ bswz));
            #pragma unroll
            for (int kk = 0; kk < 4; kk++) {
                float b0 = (kk==0)?be[0].x:(kk==1)?be[0].y:(kk==2)?be[0].z:be[0].w;
                float b1 = (kk==0)?be[1].x:(kk==1)?be[1].y:(kk==2)?be[1].z:be[1].w;
                float b2 = (kk==0)?be[2].x:(kk==1)?be[2].y:(kk==2)?be[2].z:be[2].w;
                float b3 = (kk==0)?be[3].x:(kk==1)?be[3].y:(kk==2)?be[3].z:be[3].w;
                unsigned long long pb0 = pk2(b0, b1);
                unsigned long long pb1 = pk2(b2, b3);
                #pragma unroll
                for (int f = 0; f < 4; f++) {
                    float av = (kk==0)?af[f].x:(kk==1)?af[f].y:(kk==2)?af[f].z:af[f].w;
                    unsigned long long pa = pk2(av, av);
                    acc[f][0] = fma2(pa, pb0, acc[f][0]);
                    acc[f][1] = fma2(pa, pb1, acc[f][1]);
                }
            }
        }
        if (kc + 2 < 16) issue((kc + 2) % 3, (kc + 2)*32);
        __pipeline_commit();
    }

    // merge the two k-halves: h==1 stages partials, h==0 adds + bias + store.
    __syncthreads();
    unsigned long long* red = (unsigned long long*)sm;   // 128*8 u64 = 8KB
    if (h == 1) {
        unsigned long long* dst = red + (tid - 128)*8;
        #pragma unroll
        for (int r = 0; r < 4; r++) {
            dst[2*r]     = acc[r][0];
            dst[2*r + 1] = acc[r][1];
        }
    }
    __syncthreads();
    if (h == 0) {
        const unsigned long long* src = red + tid*8;
        ulonglong2 bb = *(const ulonglong2*)&bias[nbase + tx*4];
        #pragma unroll
        for (int r = 0; r < 4; r++) {
            unsigned long long s0 = add2(acc[r][0], src[2*r]);
            unsigned long long s1 = add2(acc[r][1], src[2*r + 1]);
            ulonglong2 o;
            o.x = add2(s0, bb.x);
            o.y = add2(s1, bb.y);
            *(ulonglong2*)&C[(mbase + my*4 + r)*512 + nbase + tx*4] = o;
        }
    }
}

// ---------------------------------------------------------------------------
// R7-proven double-buffered proj (stage 1 inside fused; hidden under att)
// ---------------------------------------------------------------------------
__device__ __forceinline__ void proj_compute_chunk(
    const char* buf, int ty, int tx, unsigned long long accp[2][2])
{
    const float (*As)[33] = (const float (*)[33])buf;
    const float (*Bs)[68] = (const float (*)[68])(buf + 4224);
    #pragma unroll
    for (int k2 = 0; k2 < 32; k2++) {
        float a0 = As[k2][ty*2+0];
        float a1 = As[k2][ty*2+1];
        unsigned long long pa0 = pk2(a0, a0);
        unsigned long long pa1 = pk2(a1, a1);
        ulonglong2 bp = *(const ulonglong2*)&Bs[k2][tx*4];
        accp[0][0] = fma2(pa0, bp.x, accp[0][0]);
        accp[0][1] = fma2(pa0, bp.y, accp[0][1]);
        accp[1][0] = fma2(pa1, bp.x, accp[1][0]);
        accp[1][1] = fma2(pa1, bp.y, accp[1][1]);
    }
}

__device__ __forceinline__ void proj_sts(
    char* buf, int kk, int m0, const float ar[4], const float br[8])
{
    float (*As)[33] = (float (*)[33])buf;
    float (*Bs)[68] = (float (*)[68])(buf + 4224);
    #pragma unroll
    for (int r = 0; r < 4; r++) As[kk][m0 + 8*r] = ar[r];
    #pragma unroll
    for (int r = 0; r < 8; r++) Bs[kk][m0 + 8*r] = br[r];
}

__device__ __forceinline__ void proj_block_db(
    const float* __restrict__ A, const float* __restrict__ Wt,
    const float* __restrict__ bias, float* __restrict__ C,
    int mbase, int nbase, char* sm)
{
    const int tid = threadIdx.x;
    const int tx = tid & 15, ty = tid >> 4;
    const int kk = tid & 31;
    const int m0 = tid >> 5;

    const float* pA = A  + (mbase + m0)*512 + kk;
    const float* pB = Wt + (nbase + m0)*512 + kk;

    unsigned long long accp[2][2] = {{0ull,0ull},{0ull,0ull}};
    float ar[4], br[8];

    #pragma unroll
    for (int r = 0; r < 4; r++) ar[r] = pA[r*4096];
    #pragma unroll
    for (int r = 0; r < 8; r++) br[r] = pB[r*4096];
    proj_sts(sm, kk, m0, ar, br);
    __syncthreads();

    #pragma unroll
    for (int kc = 0; kc < 16; kc += 2) {
        if (kc + 1 < 16) {
            #pragma unroll
            for (int r = 0; r < 4; r++) ar[r] = pA[(kc+1)*32 + r*4096];
            #pragma unroll
            for (int r = 0; r < 8; r++) br[r] = pB[(kc+1)*32 + r*4096];
        }
        proj_compute_chunk(sm, ty, tx, accp);
        if (kc + 1 < 16) {
            proj_sts(sm + PROJ_BUF_BYTES, kk, m0, ar, br);
            __syncthreads();
        }
        if (kc + 1 < 16) {
            if (kc + 2 < 16) {
                #pragma unroll
                for (int r = 0; r < 4; r++) ar[r] = pA[(kc+2)*32 + r*4096];
                #pragma unroll
                for (int r = 0; r < 8; r++) br[r] = pB[(kc+2)*32 + r*4096];
            }
            proj_compute_chunk(sm + PROJ_BUF_BYTES, ty, tx, accp);
            if (kc + 2 < 16) {
                proj_sts(sm, kk, m0, ar, br);
                __syncthreads();
            }
        }
    }

    ulonglong2 bb = *(const ulonglong2*)&bias[nbase + tx*4];
    #pragma unroll
    for (int i = 0; i < 2; i++) {
        ulonglong2 o;
        o.x = add2(accp[i][0], bb.x);
        o.y = add2(accp[i][1], bb.y);
        *(ulonglong2*)&C[(mbase + ty*2 + i)*512 + nbase + tx*4] = o;
    }
}

// ---------------------------------------------------------------------------
// Stats block (256 threads): per-s head sums + collapsed att1 reductions.
// ---------------------------------------------------------------------------
__device__ __forceinline__ void stats_block(int s, char* sm)
{
    float (*pw)[6] = (float (*)[6])sm;
    float* Sv = (float*)(sm + 8*6*4);
    float* Sq = Sv + 8;
    float* Sk = Sq + 8;

    const int t = threadIdx.x;
    float v0 = g_vp[s*512 + t],      v1 = g_vp[s*512 + t + 256];
    float q0 = g_qp[s*512 + t],      q1 = g_qp[s*512 + t + 256];
    float k0 = g_kp[s*512 + t],      k1 = g_kp[s*512 + t + 256];
    #pragma unroll
    for (int d2 = 16; d2; d2 >>= 1) {
        v0 += __shfl_xor_sync(0xffffffffu, v0, d2);
        v1 += __shfl_xor_sync(0xffffffffu, v1, d2);
        q0 += __shfl_xor_sync(0xffffffffu, q0, d2);
        q1 += __shfl_xor_sync(0xffffffffu, q1, d2);
        k0 += __shfl_xor_sync(0xffffffffu, k0, d2);
        k1 += __shfl_xor_sync(0xffffffffu, k1, d2);
    }
    const int wid = t >> 5, lane = t & 31;
    if (lane == 0) {
        pw[wid][0] = v0; pw[wid][1] = q0; pw[wid][2] = k0;
        pw[wid][3] = v1; pw[wid][4] = q1; pw[wid][5] = k1;
    }
    __syncthreads();
    if (t < 8) {
        int c = t;
        if (c < 4) {
            Sv[c] = pw[2*c][0] + pw[2*c+1][0];
            Sq[c] = pw[2*c][1] + pw[2*c+1][1];
            Sk[c] = pw[2*c][2] + pw[2*c+1][2];
        } else {
            int w2 = 2*(c-4);
            Sv[c] = pw[w2][3] + pw[w2+1][3];
            Sq[c] = pw[w2][4] + pw[w2+1][4];
            Sk[c] = pw[w2][5] + pw[w2+1][5];
        }
    }
    __syncthreads();
    if (t < 64) {
        float rv = 0.f, rq = 0.f, ra = 0.f;
        #pragma unroll
        for (int cc = 0; cc < 8; cc++) {
            float sv = Sv[cc], sq = Sq[cc], sk = Sk[cc];
            rv += g_vp[s*512 + cc*64 + t] * sq * sk;
            rq += g_qp[s*512 + cc*64 + t] * sv * sk;
            ra += g_kp[s*512 + cc*64 + t] * sv * sq;
        }
        g_Rv[s*64 + t] = rv * INV_SCALE;
        g_Rq[s*64 + t] = rq * INV_SCALE;
        g_Ra[s*64 + t] = ra * INV_SCALE;
    }
}

// ---------------------------------------------------------------------------
// att block (2-barrier version): per (s,i)
//   att[j,l]*log2e = sum_c qB[c][j]*a[l][c],  qB[c][j] = u_c*q[j][c]
// u loaded per-thread via broadcast LDG.  softmax w/o max via ex2; __stcs.
// ---------------------------------------------------------------------------
__device__ __forceinline__ void att_block(int bi, float* __restrict__ osc, char* sm)
{
    float (*qB)[64]  = (float (*)[64])sm;              // [c][j]
    float (*as_)[64] = (float (*)[64])(sm + 2048);     // [c][l]
    float* reds = (float*)(sm + 4096);

    const int s = bi >> 6, i = bi & 63;
    const int t = threadIdx.x;

    #pragma unroll
    for (int r = 0; r < 2; r++) {
        int d = t + r*256;
        float u = g_vp[s*512 + (d >> 6)*64 + i] * (INV_SCALE * LOG2E);
        ((float*)qB)[d]  = g_qp[s*512 + d] * u;
        ((float*)as_)[d] = g_ap[s*512 + d];
    }
    __syncthreads();

    const int jb = (t >> 4) * 4;
    const int lb = (t & 15) * 4;

    unsigned long long pp[4][2] = {{0,0},{0,0},{0,0},{0,0}};
    #pragma unroll
    for (int c = 0; c < 8; c++) {
        float4 bq = *(const float4*)&qB[c][jb];
        ulonglong2 av = *(const ulonglong2*)&as_[c][lb];
        unsigned long long q0 = pk2(bq.x, bq.x);
        unsigned long long q1 = pk2(bq.y, bq.y);
        unsigned long long q2 = pk2(bq.z, bq.z);
        unsigned long long q3 = pk2(bq.w, bq.w);
        pp[0][0] = fma2(q0, av.x, pp[0][0]);  pp[0][1] = fma2(q0, av.y, pp[0][1]);
        pp[1][0] = fma2(q1, av.x, pp[1][0]);  pp[1][1] = fma2(q1, av.y, pp[1][1]);
        pp[2][0] = fma2(q2, av.x, pp[2][0]);  pp[2][1] = fma2(q2, av.y, pp[2][1]);
        pp[3][0] = fma2(q3, av.x, pp[3][0]);  pp[3][1] = fma2(q3, av.y, pp[3][1]);
    }

    float p[16];
    #pragma unroll
    for (int jj = 0; jj < 4; jj++) {
        upk2(p[jj*4+0], p[jj*4+1], pp[jj][0]);
        upk2(p[jj*4+2], p[jj*4+3], pp[jj][1]);
    }
    float sum = 0.f;
    #pragma unroll
    for (int e = 0; e < 16; e++) { p[e] = ex2f(p[e]); sum += p[e]; }
    #pragma unroll
    for (int d2 = 16; d2; d2 >>= 1)
        sum += __shfl_xor_sync(0xffffffffu, sum, d2);
    if ((t & 31) == 0) reds[t >> 5] = sum;
    __syncthreads();
    sum = reds[0]+reds[1]+reds[2]+reds[3]+reds[4]+reds[5]+reds[6]+reds[7];
    const float inv = __fdividef(1.0f, sum);

    float* o = osc + (size_t)bi * 4096;
    #pragma unroll
    for (int jj = 0; jj < 4; jj++) {
        float4 w4 = make_float4(p[jj*4+0]*inv, p[jj*4+1]*inv,
                                p[jj*4+2]*inv, p[jj*4+3]*inv);
        __stcs((float4*)&o[(jb+jj)*64 + lb], w4);
    }
}

// ---------------------------------------------------------------------------
// Kernel 2 (fused, reg-capped so att keeps 6 blocks/SM):
//   blocks [0,128)    : stage-1 projections (hidden under att)
//   blocks [128,256)  : stats -> g_Rv/g_Rq/g_Ra
//   blocks [256,8448) : att+softmax -> scores
// ---------------------------------------------------------------------------
__global__ __launch_bounds__(256, 6) void fused_mid_kernel(
    const float* __restrict__ Wvo, const float* __restrict__ Wqo,
    const float* __restrict__ Wao, const float* __restrict__ Wko,
    const float* __restrict__ bvo, const float* __restrict__ bqo,
    const float* __restrict__ bao, const float* __restrict__ bko,
    float* __restrict__ osc)
{
    __shared__ __align__(16) char sm[FUSED_SMEM];
    const int b = blockIdx.x;
    if (b >= 256) {
        att_block(b - 256, osc, sm);
    } else if (b < 128) {
        const int p = b & 3, mbt = (b >> 2) & 3, nbt = b >> 4;
        const float* A    = (p==0)?g_vp:(p==1)?g_qp:(p==2)?g_ap:g_kp;
        const float* Wt   = (p==0)?Wvo:(p==1)?Wqo:(p==2)?Wao:Wko;
        const float* bias = (p==0)?bvo:(p==1)?bqo:(p==2)?bao:bko;
        float* C          = (p==0)?g_vo:(p==1)?g_qo:(p==2)?g_ao:g_ko;
        proj_block_db(A, Wt, bias, C, mbt*32, nbt*64, sm);
    } else {
        stats_block(b - 128, sm);
    }
}

// ---------------------------------------------------------------------------
// Kernel 3: result writers.  256 blocks x 256 threads; c=t&7, w=t>>3
// sector-contiguous stores.
// ---------------------------------------------------------------------------
__global__ __launch_bounds__(256) void outputs_kernel(float* __restrict__ out)
{
    const int s = blockIdx.x >> 1;
    const int d = (blockIdx.x & 1)*256 + threadIdx.x;
    const int c = d & 7, w = d >> 3;
    const int src = s*512 + c*64 + w;
    out[           w*1024 + s*8 + c] = g_Rv[s*64 + w] * g_vo[src];
    out[ 65536  +  w*1024 + s*8 + c] = g_Rq[s*64 + w] * g_qo[src];
    out[131072  +  w*1024 + s*8 + c] = g_Ra[s*64 + w] * g_ao[src];
    out[196608  +  s*512  + d]       = g_ko[src];
}

// ---------------------------------------------------------------------------
// Inputs (metadata order):
//  0:v 1:q 2:a 3:k 4-7:masks(unused)
//  8:Wv 9:bv 10:Wq 11:bq 12:Wa 13:ba 14:Wk 15:bk
//  16:Wvo 17:bvo 18:Wqo 19:bqo 20:Wao 21:bao 22:Wko 23:bko
// Output: v_res | q_res | a_res | k_res | scores(33554432)
// ---------------------------------------------------------------------------
extern "C" void kernel_launch(void* const* d_in, const int* in_sizes, int n_in,
                              void* d_out, int out_size)
{
    const float* v = (const float*)d_in[0];
    const float* q = (const float*)d_in[1];
    const float* a = (const float*)d_in[2];
    const float* k = (const float*)d_in[3];
    const float* Wv  = (const float*)d_in[8];  const float* bv  = (const float*)d_in[9];
    const float* Wq  = (const float*)d_in[10]; const float* bq  = (const float*)d_in[11];
    const float* Wa  = (const float*)d_in[12]; const float* ba  = (const float*)d_in[13];
    const float* Wk  = (const float*)d_in[14]; const float* bk  = (const float*)d_in[15];
    const float* Wvo = (const float*)d_in[16]; const float* bvo = (const float*)d_in[17];
    const float* Wqo = (const float*)d_in[18]; const float* bqo = (const float*)d_in[19];
    const float* Wao = (const float*)d_in[20]; const float* bao = (const float*)d_in[21];
    const float* Wko = (const float*)d_in[22]; const float* bko = (const float*)d_in[23];
    float* out = (float*)d_out;

    dim3 gproj(8, 4, 4);   // 128 blocks x 256 threads
    proj0_kernel<<<gproj, 256>>>(v, q, a, k, Wv, Wq, Wa, Wk, bv, bq, ba, bk);
    fused_mid_kernel<<<8448, 256>>>(Wvo, Wqo, Wao, Wko, bvo, bqo, bao, bko,
                                    out + 262144);
    outputs_kernel<<<256, 256>>>(out);
}

// round 14
// speedup vs baseline: 1.0792x; 1.0792x over previous
#include <cuda_runtime.h>
#include <cuda_pipeline_primitives.h>

// Problem constants: S=128, D=512, H=8, W=64, NUM=16, SCALE=sqrt(8)
#define INV_SCALE 0.35355339059327373f
#define LOG2E     1.4426950408889634f

// Scratch (allocation-free rule: __device__ globals)
static __device__ float g_vp[128*512], g_qp[128*512], g_ap[128*512], g_kp[128*512];
static __device__ float g_vo[128*512], g_qo[128*512], g_ao[128*512], g_ko[128*512];
static __device__ float g_Rv[128*64],  g_Rq[128*64],  g_Ra[128*64];

// ---- packed f32x2 helpers (sm_103a: FFMA2 only reachable via PTX) ----------
__device__ __forceinline__ unsigned long long pk2(float x, float y) {
    unsigned long long r;
    asm("mov.b64 %0, {%1, %2};" : "=l"(r) : "f"(x), "f"(y));
    return r;
}
__device__ __forceinline__ void upk2(float& x, float& y, unsigned long long p) {
    asm("mov.b64 {%0, %1}, %2;" : "=f"(x), "=f"(y) : "l"(p));
}
__device__ __forceinline__ unsigned long long fma2(unsigned long long a,
                                                   unsigned long long b,
                                                   unsigned long long c) {
    unsigned long long d;
    asm("fma.rn.f32x2 %0, %1, %2, %3;" : "=l"(d) : "l"(a), "l"(b), "l"(c));
    return d;
}
__device__ __forceinline__ unsigned long long add2(unsigned long long a,
                                                   unsigned long long b) {
    unsigned long long d;
    asm("add.rn.f32x2 %0, %1, %2;" : "=l"(d) : "l"(a), "l"(b));
    return d;
}
__device__ __forceinline__ float ex2f(float x) {
    float r;
    asm("ex2.approx.f32 %0, %1;" : "=f"(r) : "f"(x));
    return r;
}

// ---- proj0 buffers (R10-proven): As 32x36 (4608B, stride 36 => LDS.128-
//      aligned rows of 4) + Bs 32x68 (8704B) = 13312B per stage; 3-stage ring.
#define PROJ0_A_WORDS 36
#define PROJ0_A_BYTES (32*36*4)
#define PROJ0_BUF     (PROJ0_A_BYTES + 32*68*4)   // 13312
#define PROJ0_SMEM    (3*PROJ0_BUF)               // 39936

// ---- fused-kernel proj buffers (R7/R9-proven layout, stride 33)
#define PROJ_BUF_BYTES 12928
#define FUSED_SMEM     (2*PROJ_BUF_BYTES)

// ---------------------------------------------------------------------------
// proj0 (R10-proven, 16.1us — accepted local optimum after R11-R13 falsified
// warps/blocks/layout alternatives): cp.async 3-stage pipelined GEMM,
// 4x4 micro-tile with 2-way in-chunk k-split.  C[32x64] = A[32x512]@W^T + b.
// ---------------------------------------------------------------------------
__device__ __forceinline__ void proj0_issue_chunk(
    char* buf, const float* __restrict__ pA, const float* __restrict__ pB,
    int kofs, int kk, int m0)
{
    float* As = (float*)buf;
    float* Bs = (float*)(buf + PROJ0_A_BYTES);
    #pragma unroll
    for (int r = 0; r < 4; r++)
        __pipeline_memcpy_async(&As[kk*PROJ0_A_WORDS + m0 + 8*r],
                                pA + kofs + r*4096, 4);
    #pragma unroll
    for (int r = 0; r < 8; r++)
        __pipeline_memcpy_async(&Bs[kk*68 + m0 + 8*r],
                                pB + kofs + r*4096, 4);
}

__device__ __forceinline__ void proj0_compute_half(
    const char* buf, int my, int tx, int h, unsigned long long acc[4][2])
{
    const float (*As)[PROJ0_A_WORDS] = (const float (*)[PROJ0_A_WORDS])buf;
    const float (*Bs)[68] = (const float (*)[68])(buf + PROJ0_A_BYTES);
    #pragma unroll
    for (int kk2 = 0; kk2 < 16; kk2++) {
        int k2 = h*16 + kk2;
        float4 a4 = *(const float4*)&As[k2][my*4];
        ulonglong2 bp = *(const ulonglong2*)&Bs[k2][tx*4];
        unsigned long long p0 = pk2(a4.x, a4.x);
        unsigned long long p1 = pk2(a4.y, a4.y);
        unsigned long long p2 = pk2(a4.z, a4.z);
        unsigned long long p3 = pk2(a4.w, a4.w);
        acc[0][0] = fma2(p0, bp.x, acc[0][0]);  acc[0][1] = fma2(p0, bp.y, acc[0][1]);
        acc[1][0] = fma2(p1, bp.x, acc[1][0]);  acc[1][1] = fma2(p1, bp.y, acc[1][1]);
        acc[2][0] = fma2(p2, bp.x, acc[2][0]);  acc[2][1] = fma2(p2, bp.y, acc[2][1]);
        acc[3][0] = fma2(p3, bp.x, acc[3][0]);  acc[3][1] = fma2(p3, bp.y, acc[3][1]);
    }
}

__global__ __launch_bounds__(256) void proj0_kernel(
    const float* __restrict__ v, const float* __restrict__ q,
    const float* __restrict__ a, const float* __restrict__ k,
    const float* __restrict__ Wv, const float* __restrict__ Wq,
    const float* __restrict__ Wa, const float* __restrict__ Wk,
    const float* __restrict__ bv, const float* __restrict__ bq,
    const float* __restrict__ ba, const float* __restrict__ bk)
{
    __shared__ __align__(16) char sm[PROJ0_SMEM];
    const int p = blockIdx.z;
    const float* A    = (p==0)?v:(p==1)?q:(p==2)?a:k;
    const float* Wt   = (p==0)?Wv:(p==1)?Wq:(p==2)?Wa:Wk;
    const float* bias = (p==0)?bv:(p==1)?bq:(p==2)?ba:bk;
    float* C          = (p==0)?g_vp:(p==1)?g_qp:(p==2)?g_ap:g_kp;

    const int mbase = blockIdx.y * 32;
    const int nbase = blockIdx.x * 64;
    const int tid = threadIdx.x;
    const int tx = tid & 15;
    const int my = (tid >> 4) & 7;
    const int h  = tid >> 7;          // k-half
    const int kk = tid & 31;          // fill: k within chunk
    const int m0 = tid >> 5;          // fill: row 0..7 (step 8)

    const float* pA = A  + (mbase + m0)*512 + kk;
    const float* pB = Wt + (nbase + m0)*512 + kk;

    unsigned long long acc[4][2] = {{0,0},{0,0},{0,0},{0,0}};

    proj0_issue_chunk(sm,             pA, pB, 0,  kk, m0);
    __pipeline_commit();
    proj0_issue_chunk(sm + PROJ0_BUF, pA, pB, 32, kk, m0);
    __pipeline_commit();

    #pragma unroll
    for (int kc = 0; kc < 16; kc++) {
        __pipeline_wait_prior(1);       // chunk kc landed
        __syncthreads();                // visibility + gates reuse of (kc+2)%3
        proj0_compute_half(sm + (kc % 3)*PROJ0_BUF, my, tx, h, acc);
        if (kc + 2 < 16)
            proj0_issue_chunk(sm + ((kc+2) % 3)*PROJ0_BUF,
                              pA, pB, (kc+2)*32, kk, m0);
        __pipeline_commit();            // uniform group count
    }

    // merge the two k-halves: h==1 stages partials, h==0 adds + bias + store.
    __syncthreads();
    unsigned long long* red = (unsigned long long*)sm;   // 128*8 u64 = 8KB
    if (h == 1) {
        unsigned long long* dst = red + (tid - 128)*8;
        #pragma unroll
        for (int r = 0; r < 4; r++) {
            dst[2*r]     = acc[r][0];
            dst[2*r + 1] = acc[r][1];
        }
    }
    __syncthreads();
    if (h == 0) {
        const unsigned long long* src = red + tid*8;
        ulonglong2 bb = *(const ulonglong2*)&bias[nbase + tx*4];
        #pragma unroll
        for (int r = 0; r < 4; r++) {
            unsigned long long s0 = add2(acc[r][0], src[2*r]);
            unsigned long long s1 = add2(acc[r][1], src[2*r + 1]);
            ulonglong2 o;
            o.x = add2(s0, bb.x);
            o.y = add2(s1, bb.y);
            *(ulonglong2*)&C[(mbase + my*4 + r)*512 + nbase + tx*4] = o;
        }
    }
}

// ---------------------------------------------------------------------------
// R7-proven double-buffered proj (stage 1 inside fused; hidden under att)
// ---------------------------------------------------------------------------
__device__ __forceinline__ void proj_compute_chunk(
    const char* buf, int ty, int tx, unsigned long long accp[2][2])
{
    const float (*As)[33] = (const float (*)[33])buf;
    const float (*Bs)[68] = (const float (*)[68])(buf + 4224);
    #pragma unroll
    for (int k2 = 0; k2 < 32; k2++) {
        float a0 = As[k2][ty*2+0];
        float a1 = As[k2][ty*2+1];
        unsigned long long pa0 = pk2(a0, a0);
        unsigned long long pa1 = pk2(a1, a1);
        ulonglong2 bp = *(const ulonglong2*)&Bs[k2][tx*4];
        accp[0][0] = fma2(pa0, bp.x, accp[0][0]);
        accp[0][1] = fma2(pa0, bp.y, accp[0][1]);
        accp[1][0] = fma2(pa1, bp.x, accp[1][0]);
        accp[1][1] = fma2(pa1, bp.y, accp[1][1]);
    }
}

__device__ __forceinline__ void proj_sts(
    char* buf, int kk, int m0, const float ar[4], const float br[8])
{
    float (*As)[33] = (float (*)[33])buf;
    float (*Bs)[68] = (float (*)[68])(buf + 4224);
    #pragma unroll
    for (int r = 0; r < 4; r++) As[kk][m0 + 8*r] = ar[r];
    #pragma unroll
    for (int r = 0; r < 8; r++) Bs[kk][m0 + 8*r] = br[r];
}

__device__ __forceinline__ void proj_block_db(
    const float* __restrict__ A, const float* __restrict__ Wt,
    const float* __restrict__ bias, float* __restrict__ C,
    int mbase, int nbase, char* sm)
{
    const int tid = threadIdx.x;
    const int tx = tid & 15, ty = tid >> 4;
    const int kk = tid & 31;
    const int m0 = tid >> 5;

    const float* pA = A  + (mbase + m0)*512 + kk;
    const float* pB = Wt + (nbase + m0)*512 + kk;

    unsigned long long accp[2][2] = {{0ull,0ull},{0ull,0ull}};
    float ar[4], br[8];

    #pragma unroll
    for (int r = 0; r < 4; r++) ar[r] = pA[r*4096];
    #pragma unroll
    for (int r = 0; r < 8; r++) br[r] = pB[r*4096];
    proj_sts(sm, kk, m0, ar, br);
    __syncthreads();

    #pragma unroll
    for (int kc = 0; kc < 16; kc += 2) {
        if (kc + 1 < 16) {
            #pragma unroll
            for (int r = 0; r < 4; r++) ar[r] = pA[(kc+1)*32 + r*4096];
            #pragma unroll
            for (int r = 0; r < 8; r++) br[r] = pB[(kc+1)*32 + r*4096];
        }
        proj_compute_chunk(sm, ty, tx, accp);
        if (kc + 1 < 16) {
            proj_sts(sm + PROJ_BUF_BYTES, kk, m0, ar, br);
            __syncthreads();
        }
        if (kc + 1 < 16) {
            if (kc + 2 < 16) {
                #pragma unroll
                for (int r = 0; r < 4; r++) ar[r] = pA[(kc+2)*32 + r*4096];
                #pragma unroll
                for (int r = 0; r < 8; r++) br[r] = pB[(kc+2)*32 + r*4096];
            }
            proj_compute_chunk(sm + PROJ_BUF_BYTES, ty, tx, accp);
            if (kc + 2 < 16) {
                proj_sts(sm, kk, m0, ar, br);
                __syncthreads();
            }
        }
    }

    ulonglong2 bb = *(const ulonglong2*)&bias[nbase + tx*4];
    #pragma unroll
    for (int i = 0; i < 2; i++) {
        ulonglong2 o;
        o.x = add2(accp[i][0], bb.x);
        o.y = add2(accp[i][1], bb.y);
        *(ulonglong2*)&C[(mbase + ty*2 + i)*512 + nbase + tx*4] = o;
    }
}

// ---------------------------------------------------------------------------
// Stats block (256 threads): per-s head sums + collapsed att1 reductions.
// ---------------------------------------------------------------------------
__device__ __forceinline__ void stats_block(int s, char* sm)
{
    float (*pw)[6] = (float (*)[6])sm;
    float* Sv = (float*)(sm + 8*6*4);
    float* Sq = Sv + 8;
    float* Sk = Sq + 8;

    const int t = threadIdx.x;
    float v0 = g_vp[s*512 + t],      v1 = g_vp[s*512 + t + 256];
    float q0 = g_qp[s*512 + t],      q1 = g_qp[s*512 + t + 256];
    float k0 = g_kp[s*512 + t],      k1 = g_kp[s*512 + t + 256];
    #pragma unroll
    for (int d2 = 16; d2; d2 >>= 1) {
        v0 += __shfl_xor_sync(0xffffffffu, v0, d2);
        v1 += __shfl_xor_sync(0xffffffffu, v1, d2);
        q0 += __shfl_xor_sync(0xffffffffu, q0, d2);
        q1 += __shfl_xor_sync(0xffffffffu, q1, d2);
        k0 += __shfl_xor_sync(0xffffffffu, k0, d2);
        k1 += __shfl_xor_sync(0xffffffffu, k1, d2);
    }
    const int wid = t >> 5, lane = t & 31;
    if (lane == 0) {
        pw[wid][0] = v0; pw[wid][1] = q0; pw[wid][2] = k0;
        pw[wid][3] = v1; pw[wid][4] = q1; pw[wid][5] = k1;
    }
    __syncthreads();
    if (t < 8) {
        int c = t;
        if (c < 4) {
            Sv[c] = pw[2*c][0] + pw[2*c+1][0];
            Sq[c] = pw[2*c][1] + pw[2*c+1][1];
            Sk[c] = pw[2*c][2] + pw[2*c+1][2];
        } else {
            int w2 = 2*(c-4);
            Sv[c] = pw[w2][3] + pw[w2+1][3];
            Sq[c] = pw[w2][4] + pw[w2+1][4];
            Sk[c] = pw[w2][5] + pw[w2+1][5];
        }
    }
    __syncthreads();
    if (t < 64) {
        float rv = 0.f, rq = 0.f, ra = 0.f;
        #pragma unroll
        for (int cc = 0; cc < 8; cc++) {
            float sv = Sv[cc], sq = Sq[cc], sk = Sk[cc];
            rv += g_vp[s*512 + cc*64 + t] * sq * sk;
            rq += g_qp[s*512 + cc*64 + t] * sv * sk;
            ra += g_kp[s*512 + cc*64 + t] * sv * sq;
        }
        g_Rv[s*64 + t] = rv * INV_SCALE;
        g_Rq[s*64 + t] = rq * INV_SCALE;
        g_Ra[s*64 + t] = ra * INV_SCALE;
    }
}

// ---------------------------------------------------------------------------
// att block, TWO i's per block (amortizes the i-invariant a-tile/q loads and
// halves block count; unlike R4's failed 8-i version, as_ stays in smem so
// regs are unchanged).  Per i: rebuild qB, sync, 4x4 FFMA2 tile, ex2 softmax
// w/o max, sum-reduce (its sync also protects qB for the next i), __stcs.
// ---------------------------------------------------------------------------
__device__ __forceinline__ void att_block2(int bi, float* __restrict__ osc, char* sm)
{
    float (*qB)[64]  = (float (*)[64])sm;              // [c][j]
    float (*as_)[64] = (float (*)[64])(sm + 2048);     // [c][l]
    float* reds = (float*)(sm + 4096);

    const int s = bi >> 5, i0 = (bi & 31) * 2;
    const int t = threadIdx.x;

    float qreg[2], u0[2], u1[2];
    #pragma unroll
    for (int r = 0; r < 2; r++) {
        int d = t + r*256;
        qreg[r] = g_qp[s*512 + d];
        ((float*)as_)[d] = g_ap[s*512 + d];
        int cb = (d >> 6) * 64;
        u0[r] = g_vp[s*512 + cb + i0]     * (INV_SCALE * LOG2E);
        u1[r] = g_vp[s*512 + cb + i0 + 1] * (INV_SCALE * LOG2E);
    }

    const int jb = (t >> 4) * 4;
    const int lb = (t & 15) * 4;
    float* obase = osc + (size_t)(s*64 + i0) * 4096;

    #pragma unroll
    for (int ii = 0; ii < 2; ii++) {
        // build qB for this i (safe: all qB reads of the previous i finished
        // before its reds-sync; as_ for ii==0 is covered by the sync below)
        #pragma unroll
        for (int r = 0; r < 2; r++) {
            int d = t + r*256;
            ((float*)qB)[d] = qreg[r] * (ii ? u1[r] : u0[r]);
        }
        __syncthreads();

        unsigned long long pp[4][2] = {{0,0},{0,0},{0,0},{0,0}};
        #pragma unroll
        for (int c = 0; c < 8; c++) {
            float4 bq = *(const float4*)&qB[c][jb];
            ulonglong2 av = *(const ulonglong2*)&as_[c][lb];
            unsigned long long q0 = pk2(bq.x, bq.x);
            unsigned long long q1 = pk2(bq.y, bq.y);
            unsigned long long q2 = pk2(bq.z, bq.z);
            unsigned long long q3 = pk2(bq.w, bq.w);
            pp[0][0] = fma2(q0, av.x, pp[0][0]);  pp[0][1] = fma2(q0, av.y, pp[0][1]);
            pp[1][0] = fma2(q1, av.x, pp[1][0]);  pp[1][1] = fma2(q1, av.y, pp[1][1]);
            pp[2][0] = fma2(q2, av.x, pp[2][0]);  pp[2][1] = fma2(q2, av.y, pp[2][1]);
            pp[3][0] = fma2(q3, av.x, pp[3][0]);  pp[3][1] = fma2(q3, av.y, pp[3][1]);
        }

        float p[16];
        #pragma unroll
        for (int jj = 0; jj < 4; jj++) {
            upk2(p[jj*4+0], p[jj*4+1], pp[jj][0]);
            upk2(p[jj*4+2], p[jj*4+3], pp[jj][1]);
        }
        float sum = 0.f;
        #pragma unroll
        for (int e = 0; e < 16; e++) { p[e] = ex2f(p[e]); sum += p[e]; }
        #pragma unroll
        for (int d2 = 16; d2; d2 >>= 1)
            sum += __shfl_xor_sync(0xffffffffu, sum, d2);
        if ((t & 31) == 0) reds[t >> 5] = sum;
        __syncthreads();
        sum = reds[0]+reds[1]+reds[2]+reds[3]+reds[4]+reds[5]+reds[6]+reds[7];
        const float inv = __fdividef(1.0f, sum);

        float* o = obase + ii*4096;
        #pragma unroll
        for (int jj = 0; jj < 4; jj++) {
            float4 w4 = make_float4(p[jj*4+0]*inv, p[jj*4+1]*inv,
                                    p[jj*4+2]*inv, p[jj*4+3]*inv);
            __stcs((float4*)&o[(jb+jj)*64 + lb], w4);
        }
    }
}

// ---------------------------------------------------------------------------
// Kernel 2 (fused, reg-capped so att keeps 6 blocks/SM):
//   blocks [0,128)    : stage-1 projections (hidden under att)
//   blocks [128,256)  : stats -> g_Rv/g_Rq/g_Ra
//   blocks [256,4352) : att+softmax, 2 i's per block -> scores
// ---------------------------------------------------------------------------
__global__ __launch_bounds__(256, 6) void fused_mid_kernel(
    const float* __restrict__ Wvo, const float* __restrict__ Wqo,
    const float* __restrict__ Wao, const float* __restrict__ Wko,
    const float* __restrict__ bvo, const float* __restrict__ bqo,
    const float* __restrict__ bao, const float* __restrict__ bko,
    float* __restrict__ osc)
{
    __shared__ __align__(16) char sm[FUSED_SMEM];
    const int b = blockIdx.x;
    if (b >= 256) {
        att_block2(b - 256, osc, sm);
    } else if (b < 128) {
        const int p = b & 3, mbt = (b >> 2) & 3, nbt = b >> 4;
        const float* A    = (p==0)?g_vp:(p==1)?g_qp:(p==2)?g_ap:g_kp;
        const float* Wt   = (p==0)?Wvo:(p==1)?Wqo:(p==2)?Wao:Wko;
        const float* bias = (p==0)?bvo:(p==1)?bqo:(p==2)?bao:bko;
        float* C          = (p==0)?g_vo:(p==1)?g_qo:(p==2)?g_ao:g_ko;
        proj_block_db(A, Wt, bias, C, mbt*32, nbt*64, sm);
    } else {
        stats_block(b - 128, sm);
    }
}

// ---------------------------------------------------------------------------
// Kernel 3: result writers.  256 blocks x 256 threads; c=t&7, w=t>>3
// sector-contiguous stores.
// ---------------------------------------------------------------------------
__global__ __launch_bounds__(256) void outputs_kernel(float* __restrict__ out)
{
    const int s = blockIdx.x >> 1;
    const int d = (blockIdx.x & 1)*256 + threadIdx.x;
    const int c = d & 7, w = d >> 3;
    const int src = s*512 + c*64 + w;
    out[           w*1024 + s*8 + c] = g_Rv[s*64 + w] * g_vo[src];
    out[ 65536  +  w*1024 + s*8 + c] = g_Rq[s*64 + w] * g_qo[src];
    out[131072  +  w*1024 + s*8 + c] = g_Ra[s*64 + w] * g_ao[src];
    out[196608  +  s*512  + d]       = g_ko[src];
}

// ---------------------------------------------------------------------------
// Inputs (metadata order):
//  0:v 1:q 2:a 3:k 4-7:masks(unused)
//  8:Wv 9:bv 10:Wq 11:bq 12:Wa 13:ba 14:Wk 15:bk
//  16:Wvo 17:bvo 18:Wqo 19:bqo 20:Wao 21:bao 22:Wko 23:bko
// Output: v_res | q_res | a_res | k_res | scores(33554432)
// ---------------------------------------------------------------------------
extern "C" void kernel_launch(void* const* d_in, const int* in_sizes, int n_in,
                              void* d_out, int out_size)
{
    const float* v = (const float*)d_in[0];
    const float* q = (const float*)d_in[1];
    const float* a = (const float*)d_in[2];
    const float* k = (const float*)d_in[3];
    const float* Wv  = (const float*)d_in[8];  const float* bv  = (const float*)d_in[9];
    const float* Wq  = (const float*)d_in[10]; const float* bq  = (const float*)d_in[11];
    const float* Wa  = (const float*)d_in[12]; const float* ba  = (const float*)d_in[13];
    const float* Wk  = (const float*)d_in[14]; const float* bk  = (const float*)d_in[15];
    const float* Wvo = (const float*)d_in[16]; const float* bvo = (const float*)d_in[17];
    const float* Wqo = (const float*)d_in[18]; const float* bqo = (const float*)d_in[19];
    const float* Wao = (const float*)d_in[20]; const float* bao = (const float*)d_in[21];
    const float* Wko = (const float*)d_in[22]; const float* bko = (const float*)d_in[23];
    float* out = (float*)d_out;

    dim3 gproj(8, 4, 4);   // 128 blocks x 256 threads
    proj0_kernel<<<gproj, 256>>>(v, q, a, k, Wv, Wq, Wa, Wk, bv, bq, ba, bk);
    fused_mid_kernel<<<4352, 256>>>(Wvo, Wqo, Wao, Wko, bvo, bqo, bao, bko,
                                    out + 262144);
    outputs_kernel<<<256, 256>>>(out);
}